// round 1
// baseline (speedup 1.0000x reference)
#include <cuda_runtime.h>
#include <math.h>

// ---------------- problem constants ----------------
#define BSZ   32
#define CCH   256
#define HH    64
#define WW    64

// ---------------- scratch (device globals; no allocation) ----------------
__device__ float g_y[(size_t)BSZ * CCH * HH * WW];      // conv output, 134 MB
__device__ float g_wt[CCH * 9 * CCH];                   // transposed weights [ci][k][co]
__device__ float g_ginv[2 * CCH * 64];                  // inverse circulant kernels [dir][c][n]

// ---------------- kernel 1: transpose weights ----------------
// w:  [co][ci][kh][kw]  ->  wt: [ci][k][co]
__global__ void wtrans_kernel(const float* __restrict__ w) {
    int idx = blockIdx.x * 256 + threadIdx.x;   // 256*256*9 = 589824 exact
    if (idx < CCH * CCH * 9) {
        int co  = idx / (CCH * 9);
        int rem = idx - co * (CCH * 9);
        int ci  = rem / 9;
        int k   = rem - ci * 9;
        g_wt[(ci * 9 + k) * CCH + co] = w[idx];
    }
}

// ---------------- kernel 2: build inverse circulant kernels ----------------
// alpha: (256,1,2,2). at = tanh(alpha). aw with s=sin(-pi/4), c=cos(-pi/4):
//   ax = [ (t00+t01)*r, 1, (t01-t00)*r ]   (H direction, from a=0)
//   ay = [ (t10+t11)*r, 1, (t11-t10)*r ]   (W direction, from a=1)
// Circulant system along an axis: (M y)[n] = y[n] + a2*y[n-1] + a0*y[n+1]  (mod 64)
// Inverse kernel: g[n] = (1/64) sum_u Re( e^{i th n} / F(u) ),
//   F(u) = 1 + (a0+a2) cos th + i (a0-a2) sin th,  th = 2 pi u / 64.
__global__ void ginv_kernel(const float* __restrict__ alpha) {
    int c = blockIdx.x;
    int t = threadIdx.x;          // 128 threads: dir = t>>6, n = t&63
    int dir = t >> 6;
    int n   = t & 63;

    float t00 = tanhf(alpha[c * 4 + 0]);
    float t01 = tanhf(alpha[c * 4 + 1]);
    float t10 = tanhf(alpha[c * 4 + 2]);
    float t11 = tanhf(alpha[c * 4 + 3]);
    const float R = 0.70710678118654752440f;

    float a0, a2;
    if (dir == 0) { a0 = (t00 + t01) * R; a2 = (t01 - t00) * R; }
    else          { a0 = (t10 + t11) * R; a2 = (t11 - t10) * R; }

    double ar = (double)a0 + (double)a2;
    double ai = (double)a0 - (double)a2;
    double s  = 0.0;
    for (int u = 0; u < 64; u++) {
        double th  = (2.0 * 3.14159265358979323846 / 64.0) * (double)u;
        double Fre = 1.0 + ar * cos(th);
        double Fim = ai * sin(th);
        double den = Fre * Fre + Fim * Fim;
        double ang = th * (double)n;
        s += (cos(ang) * Fre + sin(ang) * Fim) / den;
    }
    g_ginv[(dir * CCH + c) * 64 + n] = (float)(s / 64.0);
}

// ---------------- kernel 3: direct fp32 conv 3x3, pad 1 ----------------
// Block: 256 threads. Tile: 32 output channels x 8 rows x 64 cols.
// Thread: 8 co x 8 cols register tile.
// sx stride 67 -> verified conflict-free scalar LDS within a warp.
#define TCO   32
#define ROWS  8
#define CICH  4
#define SXW   67

__global__ __launch_bounds__(256, 2)
void conv3x3_kernel(const float* __restrict__ x) {
    __shared__ float sx[CICH][ROWS + 2][SXW];   // [4][10][67]
    __shared__ float sw[CICH][9][TCO];          // [4][9][32]

    const int tid = threadIdx.x;
    const int co0 = blockIdx.x * TCO;
    const int r0  = blockIdx.y * ROWS;
    const int b   = blockIdx.z;

    const int co_sub = tid >> 6;          // 0..3 -> 8 co each
    const int sp     = tid & 63;
    const int r      = sp & 7;            // 0..7
    const int c0     = (sp >> 3) << 3;    // 0,8,...,56

    float acc[8][8];
    #pragma unroll
    for (int o = 0; o < 8; o++)
        #pragma unroll
        for (int j = 0; j < 8; j++) acc[o][j] = 0.f;

    const float* xb = x + (size_t)b * CCH * HH * WW;

    for (int ci0 = 0; ci0 < CCH; ci0 += CICH) {
        // ---- stage x tile (rows r0-1 .. r0+8, cols -1..64) ----
        for (int idx = tid; idx < CICH * 10 * 66; idx += 256) {
            int ci  = idx / 660;
            int rem = idx - ci * 660;
            int row = rem / 66;
            int col = rem - row * 66;
            int gr  = r0 + row - 1;
            int gc  = col - 1;
            float v = 0.f;
            if ((unsigned)gr < HH && (unsigned)gc < WW)
                v = xb[((size_t)(ci0 + ci) * HH + gr) * WW + gc];
            sx[ci][row][col] = v;
        }
        // ---- stage w tile: wt[ci][k][co] ----
        for (int idx = tid; idx < CICH * 9 * TCO; idx += 256) {
            int co = idx & (TCO - 1);
            int k  = (idx >> 5) % 9;
            int ci = idx / (9 * TCO);
            sw[ci][k][co] = g_wt[((ci0 + ci) * 9 + k) * CCH + co0 + co];
        }
        __syncthreads();

        #pragma unroll
        for (int ci = 0; ci < CICH; ci++) {
            #pragma unroll
            for (int kh = 0; kh < 3; kh++) {
                float xv[10];
                #pragma unroll
                for (int k = 0; k < 10; k++) xv[k] = sx[ci][r + kh][c0 + k];
                #pragma unroll
                for (int kw = 0; kw < 3; kw++) {
                    const float4* wp = (const float4*)&sw[ci][kh * 3 + kw][co_sub * 8];
                    float4 w0 = wp[0], w1 = wp[1];
                    float wv[8] = {w0.x, w0.y, w0.z, w0.w, w1.x, w1.y, w1.z, w1.w};
                    #pragma unroll
                    for (int o = 0; o < 8; o++)
                        #pragma unroll
                        for (int cc = 0; cc < 8; cc++)
                            acc[o][cc] += wv[o] * xv[cc + kw];
                }
            }
        }
        __syncthreads();
    }

    // ---- write out (conv result into g_y) ----
    float* yb = g_y + (((size_t)b * CCH + co0 + co_sub * 8) * HH + (r0 + r)) * WW + c0;
    #pragma unroll
    for (int o = 0; o < 8; o++) {
        float4* yp = (float4*)(yb + (size_t)o * HH * WW);
        yp[0] = make_float4(acc[o][0], acc[o][1], acc[o][2], acc[o][3]);
        yp[1] = make_float4(acc[o][4], acc[o][5], acc[o][6], acc[o][7]);
    }
}

// ---------------- kernel 4: ARMA solve per (b,c) slice ----------------
// out = Gx * Y * Gy^T with circulant Gx[i,p] = gx[(i-p) mod 64],
// Gy[j,q] = gy[(j-q) mod 64]. Two staged 64x64x64 smem matmuls.
__global__ __launch_bounds__(256)
void arma_solve_kernel(float* __restrict__ out) {
    __shared__ float sy[64 * 64];    // Y, then reused as GyT[q][j]
    __shared__ float st[64][68];     // tmp = Gx * Y (padded stride)
    __shared__ float sgx[64];
    __shared__ float sgy[64];

    const int slice = blockIdx.x;        // b*256 + c
    const int c   = slice & 255;
    const int tid = threadIdx.x;
    const int i   = tid >> 2;            // 0..63 (row)
    const int qg  = (tid & 3) << 4;      // 0,16,32,48 (col group)

    const float* Y = g_y + (size_t)slice * 4096;
    for (int idx = tid; idx < 4096; idx += 256) sy[idx] = Y[idx];
    if (tid < 64)  sgx[tid]      = g_ginv[c * 64 + tid];
    if (tid >= 64 && tid < 128) sgy[tid - 64] = g_ginv[(CCH + c) * 64 + (tid - 64)];
    __syncthreads();

    // ---- stage 1: t[i][q] = sum_p gx[(i-p)&63] * Y[p][q] ----
    float t[16];
    #pragma unroll
    for (int k = 0; k < 16; k++) t[k] = 0.f;
    for (int p = 0; p < 64; p++) {
        float gv = sgx[(i - p) & 63];
        const float4* yp = (const float4*)&sy[p * 64 + qg];
        float4 y0 = yp[0], y1 = yp[1], y2 = yp[2], y3 = yp[3];
        t[0]  += gv * y0.x; t[1]  += gv * y0.y; t[2]  += gv * y0.z; t[3]  += gv * y0.w;
        t[4]  += gv * y1.x; t[5]  += gv * y1.y; t[6]  += gv * y1.z; t[7]  += gv * y1.w;
        t[8]  += gv * y2.x; t[9]  += gv * y2.y; t[10] += gv * y2.z; t[11] += gv * y2.w;
        t[12] += gv * y3.x; t[13] += gv * y3.y; t[14] += gv * y3.z; t[15] += gv * y3.w;
    }
    #pragma unroll
    for (int k = 0; k < 16; k += 4)
        *(float4*)&st[i][qg + k] = make_float4(t[k], t[k+1], t[k+2], t[k+3]);
    __syncthreads();   // everyone done reading sy (and writing st)

    // ---- rebuild sy as GyT[q][j] = gy[(j-q)&63] ----
    for (int idx = tid; idx < 4096; idx += 256) {
        int q = idx >> 6, j = idx & 63;
        sy[idx] = sgy[(j - q) & 63];
    }
    __syncthreads();

    // ---- stage 2: out[i][j] = sum_q t[i][q] * GyT[q][j] ----
    float o[16];
    #pragma unroll
    for (int k = 0; k < 16; k++) o[k] = 0.f;
    for (int q = 0; q < 64; q++) {
        float tv = st[i][q];
        const float4* gp = (const float4*)&sy[q * 64 + qg];
        float4 g0 = gp[0], g1 = gp[1], g2 = gp[2], g3 = gp[3];
        o[0]  += tv * g0.x; o[1]  += tv * g0.y; o[2]  += tv * g0.z; o[3]  += tv * g0.w;
        o[4]  += tv * g1.x; o[5]  += tv * g1.y; o[6]  += tv * g1.z; o[7]  += tv * g1.w;
        o[8]  += tv * g2.x; o[9]  += tv * g2.y; o[10] += tv * g2.z; o[11] += tv * g2.w;
        o[12] += tv * g3.x; o[13] += tv * g3.y; o[14] += tv * g3.z; o[15] += tv * g3.w;
    }

    float* O = out + (size_t)slice * 4096 + i * 64 + qg;
    #pragma unroll
    for (int k = 0; k < 16; k += 4)
        *(float4*)(O + k) = make_float4(o[k], o[k+1], o[k+2], o[k+3]);
}

// ---------------- launcher ----------------
extern "C" void kernel_launch(void* const* d_in, const int* in_sizes, int n_in,
                              void* d_out, int out_size) {
    const float* x     = (const float*)d_in[0];
    const float* w     = (const float*)d_in[1];
    const float* alpha = (const float*)d_in[2];
    float* out = (float*)d_out;

    wtrans_kernel<<<2304, 256>>>(w);          // 589824 / 256
    ginv_kernel<<<CCH, 128>>>(alpha);
    conv3x3_kernel<<<dim3(CCH / TCO, HH / ROWS, BSZ), 256>>>(x);
    arma_solve_kernel<<<BSZ * CCH, 256>>>(out);
}

// round 2
// speedup vs baseline: 1.0730x; 1.0730x over previous
#include <cuda_runtime.h>
#include <math.h>

// ---------------- problem constants ----------------
#define BSZ   32
#define CCH   256
#define HH    64
#define WW    64

// ---------------- scratch (device globals; no allocation) ----------------
__device__ float g_y[(size_t)BSZ * CCH * HH * WW];      // conv output, 134 MB
__device__ float g_wt[CCH * 9 * CCH];                   // transposed weights [ci][k][co]
__device__ float g_ginv[2 * CCH * 64];                  // inverse circulant kernels [dir][c][n]

// ---------------- packed f32x2 helpers ----------------
__device__ __forceinline__ unsigned long long pk2(float a, float b) {
    unsigned long long r;
    asm("mov.b64 %0, {%1, %2};" : "=l"(r) : "f"(a), "f"(b));
    return r;
}
__device__ __forceinline__ void ffma2(unsigned long long& d,
                                      unsigned long long a,
                                      unsigned long long b) {
    asm("fma.rn.f32x2 %0, %1, %2, %0;" : "+l"(d) : "l"(a), "l"(b));
}
__device__ __forceinline__ void unpk2(unsigned long long v, float& lo, float& hi) {
    asm("mov.b64 {%0, %1}, %2;" : "=f"(lo), "=f"(hi) : "l"(v));
}

// ---------------- kernel 1: transpose weights ----------------
// w:  [co][ci][kh][kw]  ->  wt: [ci][k][co]
__global__ void wtrans_kernel(const float* __restrict__ w) {
    int idx = blockIdx.x * 256 + threadIdx.x;   // 256*256*9 = 589824 exact
    if (idx < CCH * CCH * 9) {
        int co  = idx / (CCH * 9);
        int rem = idx - co * (CCH * 9);
        int ci  = rem / 9;
        int k   = rem - ci * 9;
        g_wt[(ci * 9 + k) * CCH + co] = w[idx];
    }
}

// ---------------- kernel 2: build inverse circulant kernels ----------------
// Circulant system along an axis: (M y)[n] = y[n] + a2*y[n-1] + a0*y[n+1]  (mod 64)
// Inverse kernel: g[n] = (1/64) sum_u Re( e^{i th n} / F(u) ),
//   F(u) = 1 + (a0+a2) cos th + i (a0-a2) sin th,  th = 2 pi u / 64.
__global__ void ginv_kernel(const float* __restrict__ alpha) {
    int c = blockIdx.x;
    int t = threadIdx.x;          // 128 threads: dir = t>>6, n = t&63
    int dir = t >> 6;
    int n   = t & 63;

    float t00 = tanhf(alpha[c * 4 + 0]);
    float t01 = tanhf(alpha[c * 4 + 1]);
    float t10 = tanhf(alpha[c * 4 + 2]);
    float t11 = tanhf(alpha[c * 4 + 3]);
    const float R = 0.70710678118654752440f;

    float a0, a2;
    if (dir == 0) { a0 = (t00 + t01) * R; a2 = (t01 - t00) * R; }
    else          { a0 = (t10 + t11) * R; a2 = (t11 - t10) * R; }

    double ar = (double)a0 + (double)a2;
    double ai = (double)a0 - (double)a2;
    double s  = 0.0;
    for (int u = 0; u < 64; u++) {
        double th  = (2.0 * 3.14159265358979323846 / 64.0) * (double)u;
        double Fre = 1.0 + ar * cos(th);
        double Fim = ai * sin(th);
        double den = Fre * Fre + Fim * Fim;
        double ang = th * (double)n;
        s += (cos(ang) * Fre + sin(ang) * Fim) / den;
    }
    g_ginv[(dir * CCH + c) * 64 + n] = (float)(s / 64.0);
}

// ---------------- kernel 3: direct fp32 conv 3x3, pad 1 (FFMA2) ----------------
// Block: 256 threads. Tile: 32 output channels x 8 rows x 64 cols.
// Thread: 8 co (as 4 packed co-pairs) x 8 cols.
#define TCO   32
#define ROWS  8
#define CICH  4
#define SXW   67

__global__ __launch_bounds__(256, 2)
void conv3x3_kernel(const float* __restrict__ x) {
    __shared__ float sx[CICH][ROWS + 2][SXW];   // [4][10][67]
    __shared__ float sw[CICH][9][TCO];          // [4][9][32]

    const int tid = threadIdx.x;
    const int co0 = blockIdx.x * TCO;
    const int r0  = blockIdx.y * ROWS;
    const int b   = blockIdx.z;

    const int co_sub = tid >> 6;          // 0..3 -> 8 co each
    const int sp     = tid & 63;
    const int r      = sp & 7;            // 0..7
    const int c0     = (sp >> 3) << 3;    // 0,8,...,56

    // acc2[op][c] packs (co = co_sub*8 + 2*op, co+1) for column c
    unsigned long long acc2[4][8];
    #pragma unroll
    for (int op = 0; op < 4; op++)
        #pragma unroll
        for (int c = 0; c < 8; c++) acc2[op][c] = 0ull;   // bits 0 == (0.f, 0.f)

    const float* xb = x + (size_t)b * CCH * HH * WW;

    for (int ci0 = 0; ci0 < CCH; ci0 += CICH) {
        // ---- stage x tile (rows r0-1 .. r0+8, cols -1..64) ----
        for (int idx = tid; idx < CICH * 10 * 66; idx += 256) {
            int ci  = idx / 660;
            int rem = idx - ci * 660;
            int row = rem / 66;
            int col = rem - row * 66;
            int gr  = r0 + row - 1;
            int gc  = col - 1;
            float v = 0.f;
            if ((unsigned)gr < HH && (unsigned)gc < WW)
                v = xb[((size_t)(ci0 + ci) * HH + gr) * WW + gc];
            sx[ci][row][col] = v;
        }
        // ---- stage w tile: wt[ci][k][co] ----
        for (int idx = tid; idx < CICH * 9 * TCO; idx += 256) {
            int co = idx & (TCO - 1);
            int k  = (idx >> 5) % 9;
            int ci = idx / (9 * TCO);
            sw[ci][k][co] = g_wt[((ci0 + ci) * 9 + k) * CCH + co0 + co];
        }
        __syncthreads();

        #pragma unroll
        for (int ci = 0; ci < CICH; ci++) {
            #pragma unroll
            for (int kh = 0; kh < 3; kh++) {
                float xv[10];
                #pragma unroll
                for (int k = 0; k < 10; k++) xv[k] = sx[ci][r + kh][c0 + k];
                unsigned long long xbq[10];
                #pragma unroll
                for (int k = 0; k < 10; k++) xbq[k] = pk2(xv[k], xv[k]);

                #pragma unroll
                for (int kw = 0; kw < 3; kw++) {
                    // packed co-pairs straight from shared (16B aligned)
                    const ulonglong2* wp =
                        (const ulonglong2*)&sw[ci][kh * 3 + kw][co_sub * 8];
                    ulonglong2 wa = wp[0], wb = wp[1];
                    unsigned long long wv2[4] = {wa.x, wa.y, wb.x, wb.y};
                    #pragma unroll
                    for (int op = 0; op < 4; op++)
                        #pragma unroll
                        for (int c = 0; c < 8; c++)
                            ffma2(acc2[op][c], xbq[c + kw], wv2[op]);
                }
            }
        }
        __syncthreads();
    }

    // ---- write out (conv result into g_y) ----
    #pragma unroll
    for (int op = 0; op < 4; op++) {
        int co = co_sub * 8 + 2 * op;
        float lo[8], hi[8];
        #pragma unroll
        for (int c = 0; c < 8; c++) unpk2(acc2[op][c], lo[c], hi[c]);
        float* y0 = g_y + (((size_t)b * CCH + co0 + co) * HH + (r0 + r)) * WW + c0;
        float* y1 = y0 + (size_t)HH * WW;
        ((float4*)y0)[0] = make_float4(lo[0], lo[1], lo[2], lo[3]);
        ((float4*)y0)[1] = make_float4(lo[4], lo[5], lo[6], lo[7]);
        ((float4*)y1)[0] = make_float4(hi[0], hi[1], hi[2], hi[3]);
        ((float4*)y1)[1] = make_float4(hi[4], hi[5], hi[6], hi[7]);
    }
}

// ---------------- kernel 4: ARMA solve per (b,c) slice (FFMA2) ----------------
// out = Gx * Y * Gy^T with circulant Gx[i,p] = gx[(i-p) mod 64],
// Gy[j,q] = gy[(j-q) mod 64]. Two staged 64x64x64 smem matmuls.
__global__ __launch_bounds__(256)
void arma_solve_kernel(float* __restrict__ out) {
    __shared__ float sy[64 * 64];    // Y, then reused as GyT[q][j]
    __shared__ float st[64][68];     // tmp = Gx * Y (padded stride)
    __shared__ float sgx[64];
    __shared__ float sgy[64];

    const int slice = blockIdx.x;        // b*256 + c
    const int c   = slice & 255;
    const int tid = threadIdx.x;
    const int i   = tid >> 2;            // 0..63 (row)
    const int qg  = (tid & 3) << 4;      // 0,16,32,48 (col group)

    const float* Y = g_y + (size_t)slice * 4096;
    for (int idx = tid; idx < 4096; idx += 256) sy[idx] = Y[idx];
    if (tid < 64)  sgx[tid]      = g_ginv[c * 64 + tid];
    if (tid >= 64 && tid < 128) sgy[tid - 64] = g_ginv[(CCH + c) * 64 + (tid - 64)];
    __syncthreads();

    // ---- stage 1: t[i][q] = sum_p gx[(i-p)&63] * Y[p][q] ----
    unsigned long long t2[8];
    #pragma unroll
    for (int k = 0; k < 8; k++) t2[k] = 0ull;
    for (int p = 0; p < 64; p++) {
        float gv = sgx[(i - p) & 63];
        unsigned long long gg = pk2(gv, gv);
        const ulonglong2* yp = (const ulonglong2*)&sy[p * 64 + qg];
        ulonglong2 y0 = yp[0], y1 = yp[1], y2 = yp[2], y3 = yp[3];
        ffma2(t2[0], y0.x, gg); ffma2(t2[1], y0.y, gg);
        ffma2(t2[2], y1.x, gg); ffma2(t2[3], y1.y, gg);
        ffma2(t2[4], y2.x, gg); ffma2(t2[5], y2.y, gg);
        ffma2(t2[6], y3.x, gg); ffma2(t2[7], y3.y, gg);
    }
    #pragma unroll
    for (int k = 0; k < 8; k += 2)
        *(ulonglong2*)&st[i][qg + 2 * k] = make_ulonglong2(t2[k], t2[k + 1]);
    __syncthreads();   // everyone done reading sy (and writing st)

    // ---- rebuild sy as GyT[q][j] = gy[(j-q)&63] ----
    for (int idx = tid; idx < 4096; idx += 256) {
        int q = idx >> 6, j = idx & 63;
        sy[idx] = sgy[(j - q) & 63];
    }
    __syncthreads();

    // ---- stage 2: out[i][j] = sum_q t[i][q] * GyT[q][j] ----
    unsigned long long o2[8];
    #pragma unroll
    for (int k = 0; k < 8; k++) o2[k] = 0ull;
    for (int q = 0; q < 64; q++) {
        float tv = st[i][q];
        unsigned long long tt = pk2(tv, tv);
        const ulonglong2* gp = (const ulonglong2*)&sy[q * 64 + qg];
        ulonglong2 g0 = gp[0], g1 = gp[1], g2 = gp[2], g3 = gp[3];
        ffma2(o2[0], g0.x, tt); ffma2(o2[1], g0.y, tt);
        ffma2(o2[2], g1.x, tt); ffma2(o2[3], g1.y, tt);
        ffma2(o2[4], g2.x, tt); ffma2(o2[5], g2.y, tt);
        ffma2(o2[6], g3.x, tt); ffma2(o2[7], g3.y, tt);
    }

    float* O = out + (size_t)slice * 4096 + i * 64 + qg;
    #pragma unroll
    for (int k = 0; k < 8; k += 2)
        *(ulonglong2*)(O + 2 * k) = make_ulonglong2(o2[k], o2[k + 1]);
}

// ---------------- launcher ----------------
extern "C" void kernel_launch(void* const* d_in, const int* in_sizes, int n_in,
                              void* d_out, int out_size) {
    const float* x     = (const float*)d_in[0];
    const float* w     = (const float*)d_in[1];
    const float* alpha = (const float*)d_in[2];
    float* out = (float*)d_out;

    wtrans_kernel<<<2304, 256>>>(w);          // 589824 / 256
    ginv_kernel<<<CCH, 128>>>(alpha);
    conv3x3_kernel<<<dim3(CCH / TCO, HH / ROWS, BSZ), 256>>>(x);
    arma_solve_kernel<<<BSZ * CCH, 256>>>(out);
}

// round 4
// speedup vs baseline: 1.8658x; 1.7388x over previous
#include <cuda_runtime.h>
#include <cuda_bf16.h>
#include <math.h>

// ---------------- problem constants ----------------
#define BSZ   32
#define CCH   256
#define NPIX  4096      // 64x64

// ---------------- scratch (device globals; no allocation) ----------------
__device__ float         g_y[(size_t)BSZ * CCH * NPIX];          // conv output, 134 MB
__device__ __nv_bfloat16 g_xt_hi[(size_t)BSZ * NPIX * CCH];      // x transposed [b][pix][ci]
__device__ __nv_bfloat16 g_xt_lo[(size_t)BSZ * NPIX * CCH];      // residual
__device__ __nv_bfloat16 g_wa_hi[9 * CCH * CCH];                 // weights [tap][co][ci]
__device__ __nv_bfloat16 g_wa_lo[9 * CCH * CCH];
__device__ float         g_ginv[2 * CCH * 64];                   // circulant inverses

// ---------------- helpers ----------------
__device__ __forceinline__ unsigned smem_u32(const void* p) {
    unsigned r;
    asm("{ .reg .u64 t; cvta.to.shared.u64 t, %1; cvt.u32.u64 %0, t; }" : "=r"(r) : "l"(p));
    return r;
}
__device__ __forceinline__ unsigned sw128(unsigned off) { return off ^ ((off >> 3) & 0x70); }

__device__ __forceinline__ void ldm_x4(unsigned* r, unsigned addr) {
    asm volatile("ldmatrix.sync.aligned.m8n8.x4.shared.b16 {%0,%1,%2,%3}, [%4];"
        : "=r"(r[0]), "=r"(r[1]), "=r"(r[2]), "=r"(r[3]) : "r"(addr));
}
__device__ __forceinline__ void mma16816(float* d, const unsigned* a,
                                         unsigned b0, unsigned b1) {
    asm volatile("mma.sync.aligned.m16n8k16.row.col.f32.bf16.bf16.f32 "
        "{%0,%1,%2,%3}, {%4,%5,%6,%7}, {%8,%9}, {%0,%1,%2,%3};"
        : "+f"(d[0]), "+f"(d[1]), "+f"(d[2]), "+f"(d[3])
        : "r"(a[0]), "r"(a[1]), "r"(a[2]), "r"(a[3]), "r"(b0), "r"(b1));
}

// packed f32x2 helpers (arma)
__device__ __forceinline__ unsigned long long pk2(float a, float b) {
    unsigned long long r;
    asm("mov.b64 %0, {%1, %2};" : "=l"(r) : "f"(a), "f"(b));
    return r;
}
__device__ __forceinline__ void ffma2(unsigned long long& d, unsigned long long a,
                                      unsigned long long b) {
    asm("fma.rn.f32x2 %0, %1, %2, %0;" : "+l"(d) : "l"(a), "l"(b));
}

// ---------------- kernel 1: weights -> [tap][co][ci] bf16 hi/lo ----------------
__global__ void wa_kernel(const float* __restrict__ w) {
    int tap = blockIdx.x >> 8;
    int co  = blockIdx.x & 255;
    int ci  = threadIdx.x;
    float v = w[((size_t)co * 256 + ci) * 9 + tap];
    __nv_bfloat16 h = __float2bfloat16(v);
    __nv_bfloat16 l = __float2bfloat16(v - __bfloat162float(h));
    size_t o = ((size_t)tap * 256 + co) * 256 + ci;
    g_wa_hi[o] = h; g_wa_lo[o] = l;
}

// ---------------- kernel 2: x -> transposed bf16 hi/lo ----------------
__global__ void xt_kernel(const float* __restrict__ x) {
    __shared__ float s[64][65];
    int p0  = blockIdx.x * 64;
    int ci0 = blockIdx.y * 64;
    int b   = blockIdx.z;
    int tid = threadIdx.x;
    for (int i = tid; i < 4096; i += 256) {
        int ci = i >> 6, p = i & 63;
        s[ci][p] = x[((size_t)(b * 256 + ci0 + ci)) * NPIX + p0 + p];
    }
    __syncthreads();
    for (int i = tid; i < 4096; i += 256) {
        int pix = i >> 6, ci = i & 63;
        float v = s[ci][pix];
        __nv_bfloat16 h = __float2bfloat16(v);
        __nv_bfloat16 l = __float2bfloat16(v - __bfloat162float(h));
        size_t o = ((size_t)b * NPIX + p0 + pix) * 256 + ci0 + ci;
        g_xt_hi[o] = h; g_xt_lo[o] = l;
    }
}

// ---------------- kernel 3: circulant inverse kernels ----------------
__global__ void ginv_kernel(const float* __restrict__ alpha) {
    int c = blockIdx.x;
    int t = threadIdx.x;
    int dir = t >> 6;
    int n   = t & 63;
    float t00 = tanhf(alpha[c*4+0]), t01 = tanhf(alpha[c*4+1]);
    float t10 = tanhf(alpha[c*4+2]), t11 = tanhf(alpha[c*4+3]);
    const float R = 0.70710678118654752440f;
    float a0, a2;
    if (dir == 0) { a0 = (t00 + t01) * R; a2 = (t01 - t00) * R; }
    else          { a0 = (t10 + t11) * R; a2 = (t11 - t10) * R; }
    double ar = (double)a0 + (double)a2;
    double ai = (double)a0 - (double)a2;
    double s = 0.0;
    for (int u = 0; u < 64; u++) {
        double th  = (2.0 * 3.14159265358979323846 / 64.0) * (double)u;
        double Fre = 1.0 + ar * cos(th);
        double Fim = ai * sin(th);
        double den = Fre * Fre + Fim * Fim;
        double ang = th * (double)n;
        s += (cos(ang) * Fre + sin(ang) * Fim) / den;
    }
    g_ginv[(dir * CCH + c) * 64 + n] = (float)(s / 64.0);
}

// ---------------- kernel 4: implicit-GEMM conv via mma.sync (HMMA) ----------------
// CTA: M=128 co x N=256 pixels (4 image rows). 512 threads = 16 warps (2M x 8N).
// Warp tile 64x32. K loop: 4 ci-chunks of 64 x 9 taps x 3 hi/lo terms.
// X patch (6 h-rows x 68 w x 64 ci) staged once per ci-chunk, reused by all taps.
// SMEM byte layout:
#define XPAT_ROWS  (6 * 68)            // row = 128 B (64 ci bf16)
#define XPAT_BYTES (XPAT_ROWS * 128)   // 52224
#define OFF_XH 0u
#define OFF_XL (OFF_XH + XPAT_BYTES)
#define OFF_AH (OFF_XL + XPAT_BYTES)   // 104448; A tile = 128 co x 64 ci = 16384 B
#define OFF_AL (OFF_AH + 16384u)
#define CONV_SMEM (OFF_AL + 16384)     // 137216

__global__ __launch_bounds__(512, 1)
void conv_mma_kernel() {
    extern __shared__ char smem[];
    const unsigned sb = smem_u32(smem);
    const int tid = threadIdx.x;
    const int lid = tid & 31;
    const int wid = tid >> 5;
    const int wm  = wid & 1;            // 0..1  (64 co each)
    const int wn  = wid >> 1;           // 0..7  (32 pixels each)

    const int n0  = blockIdx.x * 256;   // pixel base (4 image rows)
    const int h0  = n0 >> 6;
    const int co0 = blockIdx.y * 128;
    const int b   = blockIdx.z;

    const __nv_bfloat16* xh = g_xt_hi + (size_t)b * NPIX * 256;
    const __nv_bfloat16* xl = g_xt_lo + (size_t)b * NPIX * 256;

    float acc[4][4][4];
    #pragma unroll
    for (int mt = 0; mt < 4; mt++)
        #pragma unroll
        for (int nt = 0; nt < 4; nt++)
            #pragma unroll
            for (int k = 0; k < 4; k++) acc[mt][nt][k] = 0.f;

    // A ldmatrix lane geometry (tap/chunk independent): byte row offset + k8 part
    unsigned a_rowoff[4];
    #pragma unroll
    for (int mt = 0; mt < 4; mt++) {
        int row = wm * 64 + mt * 16 + (lid & 7) + ((lid >> 3) & 1) * 8;
        a_rowoff[mt] = (unsigned)(row * 128) + ((unsigned)(lid >> 4)) * 16u;
    }
    // B lane row pixel coords (n within CTA tile)
    const int bn[2] = { wn * 32 + (lid & 15), wn * 32 + 16 + (lid & 15) };
    const unsigned bk8 = ((unsigned)(lid >> 4)) * 16u;

    for (int cc = 0; cc < 4; cc++) {
        const int ci0 = cc << 6;
        __syncthreads();    // previous compute (X + A reads) finished
        // ---- stage X patch: rows h0-1..h0+4, cols -1..64 -> [hl][wv][ci] ----
        #pragma unroll 2
        for (int sp = 0; sp < 2; sp++) {
            const __nv_bfloat16* src = sp ? xl : xh;
            char* dstb = smem + (sp ? OFF_XL : OFF_XH);
            for (int i = tid; i < 6 * 66 * 8; i += 512) {
                int cq  = i & 7;
                int row = i >> 3;          // 0..395
                int hl  = row / 66;
                int wv  = row - hl * 66;
                int h = h0 + hl - 1;
                int w = wv - 1;
                uint4 v = make_uint4(0, 0, 0, 0);
                if ((unsigned)h < 64u && (unsigned)w < 64u)
                    v = *(const uint4*)(src + ((size_t)(h * 64 + w)) * 256 + ci0 + cq * 8);
                *(uint4*)(dstb + sw128((unsigned)((hl * 68 + wv) * 128 + cq * 16))) = v;
            }
        }

        for (int tap = 0; tap < 9; tap++) {
            const int dh = tap / 3 - 1;
            const int dw = tap % 3 - 1;
            __syncthreads();   // X staged (tap 0) / previous tap's A reads finished
            // ---- stage A tile [128 co][64 ci] hi+lo ----
            #pragma unroll 2
            for (int sp = 0; sp < 2; sp++) {
                const __nv_bfloat16* src = sp ? g_wa_lo : g_wa_hi;
                char* dstb = smem + (sp ? OFF_AL : OFF_AH);
                #pragma unroll
                for (int i = tid; i < 1024; i += 512) {
                    int cq = i & 7, row = i >> 3;
                    uint4 v = *(const uint4*)(src +
                        ((size_t)tap * 256 + co0 + row) * 256 + ci0 + cq * 8);
                    *(uint4*)(dstb + sw128((unsigned)(row * 128 + cq * 16))) = v;
                }
            }
            __syncthreads();

            // B lane row byte offsets for this tap
            unsigned b_rowoff[2];
            #pragma unroll
            for (int j = 0; j < 2; j++) {
                int hl = bn[j] >> 6, w = bn[j] & 63;
                b_rowoff[j] = (unsigned)(((hl + dh + 1) * 68 + (w + dw + 1)) * 128) + bk8;
            }

            // ---- 3 terms: (Ah,Bh), (Ah,Bl), (Al,Bh) ----
            #pragma unroll
            for (int term = 0; term < 3; term++) {
                const unsigned Abase = sb + (term == 2 ? OFF_AL : OFF_AH);
                const unsigned Bbase = sb + (term == 1 ? OFF_XL : OFF_XH);
                #pragma unroll
                for (int ks = 0; ks < 4; ks++) {
                    unsigned af[4][4];
                    #pragma unroll
                    for (int mt = 0; mt < 4; mt++)
                        ldm_x4(af[mt], Abase + sw128(a_rowoff[mt] + ks * 32u));
                    unsigned bf[2][4];
                    #pragma unroll
                    for (int j = 0; j < 2; j++)
                        ldm_x4(bf[j], Bbase + sw128(b_rowoff[j] + ks * 32u));
                    #pragma unroll
                    for (int mt = 0; mt < 4; mt++) {
                        #pragma unroll
                        for (int nt = 0; nt < 4; nt++)
                            mma16816(acc[mt][nt], af[mt],
                                     bf[nt >> 1][nt & 1], bf[nt >> 1][(nt & 1) + 2]);
                    }
                }
            }
        }
    }

    // ---- epilogue: direct stores to g_y [b*256+co][pix] ----
    const int r4 = lid >> 2, c2 = (lid & 3) << 1;
    #pragma unroll
    for (int mt = 0; mt < 4; mt++) {
        #pragma unroll
        for (int nt = 0; nt < 4; nt++) {
            int co  = co0 + wm * 64 + mt * 16 + r4;
            int pix = n0 + wn * 32 + nt * 8 + c2;
            float* p = g_y + ((size_t)(b * 256 + co)) * NPIX + pix;
            *(float2*)p = make_float2(acc[mt][nt][0], acc[mt][nt][1]);
            *(float2*)(p + (size_t)8 * NPIX) = make_float2(acc[mt][nt][2], acc[mt][nt][3]);
        }
    }
}

// ---------------- kernel 5: ARMA solve, 4x4 register tiling ----------------
__global__ __launch_bounds__(256)
void arma_solve_kernel(float* __restrict__ out) {
    __shared__ float sy[64 * 64];
    __shared__ float st[64][68];
    __shared__ float sgx[64];
    __shared__ float sgy[64];

    const int slice = blockIdx.x;
    const int c   = slice & 255;
    const int tid = threadIdx.x;
    const int ig  = (tid >> 4) << 2;   // 0,4,...,60
    const int qg  = (tid & 15) << 2;   // 0,4,...,60

    const float* Y = g_y + (size_t)slice * 4096;
    for (int idx = tid; idx < 4096; idx += 256) sy[idx] = Y[idx];
    if (tid < 64)                sgx[tid]      = g_ginv[c * 64 + tid];
    if (tid >= 64 && tid < 128)  sgy[tid - 64] = g_ginv[(CCH + c) * 64 + (tid - 64)];
    __syncthreads();

    // stage 1: t[i][q] = sum_p gx[(i-p)&63] * Y[p][q]
    unsigned long long acc[4][2];
    #pragma unroll
    for (int k = 0; k < 4; k++) { acc[k][0] = 0ull; acc[k][1] = 0ull; }
    for (int p = 0; p < 64; p++) {
        unsigned long long gp[4];
        #pragma unroll
        for (int k = 0; k < 4; k++) {
            float gv = sgx[(ig + k - p) & 63];
            gp[k] = pk2(gv, gv);
        }
        ulonglong2 y2 = *(const ulonglong2*)&sy[p * 64 + qg];
        #pragma unroll
        for (int k = 0; k < 4; k++) { ffma2(acc[k][0], y2.x, gp[k]); ffma2(acc[k][1], y2.y, gp[k]); }
    }
    #pragma unroll
    for (int k = 0; k < 4; k++)
        *(ulonglong2*)&st[ig + k][qg] = make_ulonglong2(acc[k][0], acc[k][1]);
    __syncthreads();

    // rebuild sy as GyT[q][j] = gy[(j-q)&63]
    for (int idx = tid; idx < 4096; idx += 256) {
        int q = idx >> 6, j = idx & 63;
        sy[idx] = sgy[(j - q) & 63];
    }
    __syncthreads();

    // stage 2: out[i][j] = sum_q t[i][q] * GyT[q][j]
    unsigned long long o2[4][2];
    #pragma unroll
    for (int k = 0; k < 4; k++) { o2[k][0] = 0ull; o2[k][1] = 0ull; }
    for (int q = 0; q < 64; q++) {
        unsigned long long tp[4];
        #pragma unroll
        for (int k = 0; k < 4; k++) {
            float tv = st[ig + k][q];
            tp[k] = pk2(tv, tv);
        }
        ulonglong2 g2 = *(const ulonglong2*)&sy[q * 64 + qg];
        #pragma unroll
        for (int k = 0; k < 4; k++) { ffma2(o2[k][0], g2.x, tp[k]); ffma2(o2[k][1], g2.y, tp[k]); }
    }
    float* O = out + (size_t)slice * 4096;
    #pragma unroll
    for (int k = 0; k < 4; k++)
        *(ulonglong2*)(O + (ig + k) * 64 + qg) = make_ulonglong2(o2[k][0], o2[k][1]);
}

// ---------------- launcher ----------------
extern "C" void kernel_launch(void* const* d_in, const int* in_sizes, int n_in,
                              void* d_out, int out_size) {
    const float* x     = (const float*)d_in[0];
    const float* w     = (const float*)d_in[1];
    const float* alpha = (const float*)d_in[2];
    float* out = (float*)d_out;

    cudaFuncSetAttribute(conv_mma_kernel,
                         cudaFuncAttributeMaxDynamicSharedMemorySize, CONV_SMEM);

    wa_kernel<<<9 * 256, 256>>>(w);
    ginv_kernel<<<CCH, 128>>>(alpha);
    xt_kernel<<<dim3(64, 4, 32), 256>>>(x);
    conv_mma_kernel<<<dim3(16, 2, 32), 512, CONV_SMEM>>>();
    arma_solve_kernel<<<BSZ * CCH, 256>>>(out);
}

// round 5
// speedup vs baseline: 2.5657x; 1.3751x over previous
#include <cuda_runtime.h>
#include <cuda_bf16.h>
#include <math.h>

// ---------------- problem constants ----------------
#define BSZ   32
#define CCH   256
#define NPIX  4096      // 64x64

// ---------------- scratch (device globals; no allocation) ----------------
__device__ float                        g_y[(size_t)BSZ * CCH * NPIX];
__device__ __align__(16) __nv_bfloat16  g_xt_hi[(size_t)BSZ * NPIX * CCH];
__device__ __align__(16) __nv_bfloat16  g_xt_lo[(size_t)BSZ * NPIX * CCH];
__device__ __align__(16) __nv_bfloat16  g_wa_hi[9 * CCH * CCH];
__device__ __align__(16) __nv_bfloat16  g_wa_lo[9 * CCH * CCH];
__device__ float                        g_ginv[2 * CCH * 64];

// ---------------- helpers ----------------
__device__ __forceinline__ unsigned smem_u32(const void* p) {
    unsigned r;
    asm("{ .reg .u64 t; cvta.to.shared.u64 t, %1; cvt.u32.u64 %0, t; }" : "=r"(r) : "l"(p));
    return r;
}
__device__ __forceinline__ unsigned sw128(unsigned off) { return off ^ ((off >> 3) & 0x70); }

__device__ __forceinline__ void ldm_x4(unsigned* r, unsigned addr) {
    asm volatile("ldmatrix.sync.aligned.m8n8.x4.shared.b16 {%0,%1,%2,%3}, [%4];"
        : "=r"(r[0]), "=r"(r[1]), "=r"(r[2]), "=r"(r[3]) : "r"(addr));
}
__device__ __forceinline__ void mma16816(float* d, const unsigned* a,
                                         unsigned b0, unsigned b1) {
    asm volatile("mma.sync.aligned.m16n8k16.row.col.f32.bf16.bf16.f32 "
        "{%0,%1,%2,%3}, {%4,%5,%6,%7}, {%8,%9}, {%0,%1,%2,%3};"
        : "+f"(d[0]), "+f"(d[1]), "+f"(d[2]), "+f"(d[3])
        : "r"(a[0]), "r"(a[1]), "r"(a[2]), "r"(a[3]), "r"(b0), "r"(b1));
}
__device__ __forceinline__ void cp16(unsigned dst, const void* src) {
    asm volatile("cp.async.cg.shared.global [%0], [%1], 16;" :: "r"(dst), "l"(src));
}
__device__ __forceinline__ void cp_commit() {
    asm volatile("cp.async.commit_group;" ::: "memory");
}
__device__ __forceinline__ void cp_wait0() {
    asm volatile("cp.async.wait_group 0;" ::: "memory");
}

// packed f32x2 helpers (arma)
__device__ __forceinline__ unsigned long long pk2(float a, float b) {
    unsigned long long r;
    asm("mov.b64 %0, {%1, %2};" : "=l"(r) : "f"(a), "f"(b));
    return r;
}
__device__ __forceinline__ void ffma2(unsigned long long& d, unsigned long long a,
                                      unsigned long long b) {
    asm("fma.rn.f32x2 %0, %1, %2, %0;" : "+l"(d) : "l"(a), "l"(b));
}

// ---------------- kernel 1: weights -> [tap][co][ci] bf16 hi/lo ----------------
__global__ void wa_kernel(const float* __restrict__ w) {
    int tap = blockIdx.x >> 8;
    int co  = blockIdx.x & 255;
    int ci  = threadIdx.x;
    float v = w[((size_t)co * 256 + ci) * 9 + tap];
    __nv_bfloat16 h = __float2bfloat16(v);
    __nv_bfloat16 l = __float2bfloat16(v - __bfloat162float(h));
    size_t o = ((size_t)tap * 256 + co) * 256 + ci;
    g_wa_hi[o] = h; g_wa_lo[o] = l;
}

// ---------------- kernel 2: x -> transposed bf16 hi/lo ----------------
__global__ void xt_kernel(const float* __restrict__ x) {
    __shared__ float s[64][65];
    int p0  = blockIdx.x * 64;
    int ci0 = blockIdx.y * 64;
    int b   = blockIdx.z;
    int tid = threadIdx.x;
    for (int i = tid; i < 4096; i += 256) {
        int ci = i >> 6, p = i & 63;
        s[ci][p] = x[((size_t)(b * 256 + ci0 + ci)) * NPIX + p0 + p];
    }
    __syncthreads();
    for (int i = tid; i < 4096; i += 256) {
        int pix = i >> 6, ci = i & 63;
        float v = s[ci][pix];
        __nv_bfloat16 h = __float2bfloat16(v);
        __nv_bfloat16 l = __float2bfloat16(v - __bfloat162float(h));
        size_t o = ((size_t)b * NPIX + p0 + pix) * 256 + ci0 + ci;
        g_xt_hi[o] = h; g_xt_lo[o] = l;
    }
}

// ---------------- kernel 3: circulant inverse kernels ----------------
__global__ void ginv_kernel(const float* __restrict__ alpha) {
    int c = blockIdx.x;
    int t = threadIdx.x;
    int dir = t >> 6;
    int n   = t & 63;
    float t00 = tanhf(alpha[c*4+0]), t01 = tanhf(alpha[c*4+1]);
    float t10 = tanhf(alpha[c*4+2]), t11 = tanhf(alpha[c*4+3]);
    const float R = 0.70710678118654752440f;
    float a0, a2;
    if (dir == 0) { a0 = (t00 + t01) * R; a2 = (t01 - t00) * R; }
    else          { a0 = (t10 + t11) * R; a2 = (t11 - t10) * R; }
    double ar = (double)a0 + (double)a2;
    double ai = (double)a0 - (double)a2;
    double s = 0.0;
    for (int u = 0; u < 64; u++) {
        double th  = (2.0 * 3.14159265358979323846 / 64.0) * (double)u;
        double Fre = 1.0 + ar * cos(th);
        double Fim = ai * sin(th);
        double den = Fre * Fre + Fim * Fim;
        double ang = th * (double)n;
        s += (cos(ang) * Fre + sin(ang) * Fim) / den;
    }
    g_ginv[(dir * CCH + c) * 64 + n] = (float)(s / 64.0);
}

// ---------------- kernel 4: implicit-GEMM conv via mma.sync ----------------
// CTA: M=128 co x N=256 pixels. 256 threads = 8 warps (2M x 4N), warp tile 64x64.
// K: 4 ci-chunks of 64 x 9 taps x 3 hi/lo terms with fragment sharing.
// A (weights) double-buffered via cp.async across taps.
#define XPAT_ROWS  (6 * 68)
#define XPAT_BYTES (XPAT_ROWS * 128)   // 52224
#define OFF_XH 0u
#define OFF_XL (OFF_XH + XPAT_BYTES)
#define OFF_A0 (OFF_XL + XPAT_BYTES)   // 104448; per buf: hi 16384 + lo 16384
#define A_BUF  32768u
#define A_LO   16384u
#define CONV_SMEM (OFF_A0 + 2 * A_BUF) // 169984

__global__ __launch_bounds__(256, 1)
void conv_mma_kernel() {
    extern __shared__ char smem[];
    const unsigned sb = smem_u32(smem);
    const int tid = threadIdx.x;
    const int lid = tid & 31;
    const int wid = tid >> 5;
    const int wm  = wid & 1;            // 0..1 (64 co each)
    const int wn  = wid >> 1;           // 0..3 (64 pixels each)

    const int n0  = blockIdx.x * 256;   // pixel base (4 image rows)
    const int h0  = n0 >> 6;
    const int co0 = blockIdx.y * 128;
    const int b   = blockIdx.z;

    const __nv_bfloat16* xh = g_xt_hi + (size_t)b * NPIX * 256;
    const __nv_bfloat16* xl = g_xt_lo + (size_t)b * NPIX * 256;

    float acc[4][8][4];
    #pragma unroll
    for (int mt = 0; mt < 4; mt++)
        #pragma unroll
        for (int nt = 0; nt < 8; nt++)
            #pragma unroll
            for (int k = 0; k < 4; k++) acc[mt][nt][k] = 0.f;

    // A ldmatrix lane geometry
    unsigned a_rowoff[4];
    #pragma unroll
    for (int mt = 0; mt < 4; mt++) {
        int row = wm * 64 + mt * 16 + (lid & 7) + ((lid >> 3) & 1) * 8;
        a_rowoff[mt] = (unsigned)(row * 128) + ((unsigned)(lid >> 4)) * 16u;
    }
    // B lane row pixel coords: 4 n16-tiles covering 64 pixels
    int bn[4];
    #pragma unroll
    for (int j = 0; j < 4; j++) bn[j] = wn * 64 + j * 16 + (lid & 15);
    const unsigned bk8 = ((unsigned)(lid >> 4)) * 16u;

    // cp.async A staging (4 x 16B hi + 4 x 16B lo per thread)
    auto stageA = [&](int tap, int ci0, int s) {
        unsigned dH = sb + OFF_A0 + (unsigned)s * A_BUF;
        unsigned dL = dH + A_LO;
        #pragma unroll
        for (int i = tid; i < 1024; i += 256) {
            int cq = i & 7, row = i >> 3;
            size_t src = ((size_t)tap * 256 + co0 + row) * 256 + ci0 + cq * 8;
            unsigned swo = sw128((unsigned)(row * 128 + cq * 16));
            cp16(dH + swo, g_wa_hi + src);
            cp16(dL + swo, g_wa_lo + src);
        }
        cp_commit();
    };

    for (int cc = 0; cc < 4; cc++) {
        const int ci0 = cc << 6;
        __syncthreads();    // previous chunk's compute done (XPAT + A free)
        // ---- stage X patch: rows h0-1..h0+4, cols -1..64 -> [hl][wv][ci] ----
        #pragma unroll 2
        for (int sp = 0; sp < 2; sp++) {
            const __nv_bfloat16* src = sp ? xl : xh;
            char* dstb = smem + (sp ? OFF_XL : OFF_XH);
            for (int i = tid; i < 6 * 66 * 8; i += 256) {
                int cq  = i & 7;
                int row = i >> 3;
                int hl  = row / 66;
                int wv  = row - hl * 66;
                int h = h0 + hl - 1;
                int w = wv - 1;
                uint4 v = make_uint4(0, 0, 0, 0);
                if ((unsigned)h < 64u && (unsigned)w < 64u)
                    v = *(const uint4*)(src + ((size_t)(h * 64 + w)) * 256 + ci0 + cq * 8);
                *(uint4*)(dstb + sw128((unsigned)((hl * 68 + wv) * 128 + cq * 16))) = v;
            }
        }
        stageA(0, ci0, 0);
        cp_wait0();
        __syncthreads();    // X + A(tap0) visible

        for (int tap = 0; tap < 9; tap++) {
            const int s  = tap & 1;
            const int dh = tap / 3 - 1;
            const int dw = tap % 3 - 1;
            if (tap < 8) stageA(tap + 1, ci0, s ^ 1);   // prefetch next tap's A

            const unsigned AH = sb + OFF_A0 + (unsigned)s * A_BUF;
            const unsigned AL = AH + A_LO;

            unsigned b_rowoff[4];
            #pragma unroll
            for (int j = 0; j < 4; j++) {
                int hl = bn[j] >> 6, w = bn[j] & 63;
                b_rowoff[j] = (unsigned)(((hl + dh + 1) * 68 + (w + dw + 1)) * 128) + bk8;
            }

            #pragma unroll
            for (int ks = 0; ks < 4; ks++) {
                unsigned afH[4][4], afL[4][4], bfH[4][4], bfL[4][4];
                #pragma unroll
                for (int mt = 0; mt < 4; mt++)
                    ldm_x4(afH[mt], AH + sw128(a_rowoff[mt] + ks * 32u));
                #pragma unroll
                for (int j = 0; j < 4; j++)
                    ldm_x4(bfH[j], sb + OFF_XH + sw128(b_rowoff[j] + ks * 32u));
                // term HH
                #pragma unroll
                for (int mt = 0; mt < 4; mt++)
                    #pragma unroll
                    for (int nt = 0; nt < 8; nt++)
                        mma16816(acc[mt][nt], afH[mt],
                                 bfH[nt >> 1][nt & 1], bfH[nt >> 1][(nt & 1) + 2]);
                #pragma unroll
                for (int j = 0; j < 4; j++)
                    ldm_x4(bfL[j], sb + OFF_XL + sw128(b_rowoff[j] + ks * 32u));
                // term HL (reuse afH)
                #pragma unroll
                for (int mt = 0; mt < 4; mt++)
                    #pragma unroll
                    for (int nt = 0; nt < 8; nt++)
                        mma16816(acc[mt][nt], afH[mt],
                                 bfL[nt >> 1][nt & 1], bfL[nt >> 1][(nt & 1) + 2]);
                #pragma unroll
                for (int mt = 0; mt < 4; mt++)
                    ldm_x4(afL[mt], AL + sw128(a_rowoff[mt] + ks * 32u));
                // term LH (reuse bfH)
                #pragma unroll
                for (int mt = 0; mt < 4; mt++)
                    #pragma unroll
                    for (int nt = 0; nt < 8; nt++)
                        mma16816(acc[mt][nt], afL[mt],
                                 bfH[nt >> 1][nt & 1], bfH[nt >> 1][(nt & 1) + 2]);
            }
            if (tap < 8) {
                cp_wait0();
                __syncthreads();   // next A landed; all warps done with this tap
            }
        }
    }

    // ---- epilogue: direct stores to g_y ----
    const int r4 = lid >> 2, c2 = (lid & 3) << 1;
    #pragma unroll
    for (int mt = 0; mt < 4; mt++) {
        #pragma unroll
        for (int nt = 0; nt < 8; nt++) {
            int co  = co0 + wm * 64 + mt * 16 + r4;
            int pix = n0 + wn * 64 + nt * 8 + c2;
            float* p = g_y + ((size_t)(b * 256 + co)) * NPIX + pix;
            *(float2*)p = make_float2(acc[mt][nt][0], acc[mt][nt][1]);
            *(float2*)(p + (size_t)8 * NPIX) = make_float2(acc[mt][nt][2], acc[mt][nt][3]);
        }
    }
}

// ---------------- kernel 5: ARMA solve, 4x4 register tiling ----------------
__global__ __launch_bounds__(256)
void arma_solve_kernel(float* __restrict__ out) {
    __shared__ float sy[64 * 64];
    __shared__ float st[64][68];
    __shared__ float sgx[64];
    __shared__ float sgy[64];

    const int slice = blockIdx.x;
    const int c   = slice & 255;
    const int tid = threadIdx.x;
    const int ig  = (tid >> 4) << 2;
    const int qg  = (tid & 15) << 2;

    const float* Y = g_y + (size_t)slice * 4096;
    for (int idx = tid; idx < 4096; idx += 256) sy[idx] = Y[idx];
    if (tid < 64)                sgx[tid]      = g_ginv[c * 64 + tid];
    if (tid >= 64 && tid < 128)  sgy[tid - 64] = g_ginv[(CCH + c) * 64 + (tid - 64)];
    __syncthreads();

    unsigned long long acc[4][2];
    #pragma unroll
    for (int k = 0; k < 4; k++) { acc[k][0] = 0ull; acc[k][1] = 0ull; }
    for (int p = 0; p < 64; p++) {
        unsigned long long gp[4];
        #pragma unroll
        for (int k = 0; k < 4; k++) {
            float gv = sgx[(ig + k - p) & 63];
            gp[k] = pk2(gv, gv);
        }
        ulonglong2 y2 = *(const ulonglong2*)&sy[p * 64 + qg];
        #pragma unroll
        for (int k = 0; k < 4; k++) { ffma2(acc[k][0], y2.x, gp[k]); ffma2(acc[k][1], y2.y, gp[k]); }
    }
    #pragma unroll
    for (int k = 0; k < 4; k++)
        *(ulonglong2*)&st[ig + k][qg] = make_ulonglong2(acc[k][0], acc[k][1]);
    __syncthreads();

    for (int idx = tid; idx < 4096; idx += 256) {
        int q = idx >> 6, j = idx & 63;
        sy[idx] = sgy[(j - q) & 63];
    }
    __syncthreads();

    unsigned long long o2[4][2];
    #pragma unroll
    for (int k = 0; k < 4; k++) { o2[k][0] = 0ull; o2[k][1] = 0ull; }
    for (int q = 0; q < 64; q++) {
        unsigned long long tp[4];
        #pragma unroll
        for (int k = 0; k < 4; k++) {
            float tv = st[ig + k][q];
            tp[k] = pk2(tv, tv);
        }
        ulonglong2 g2 = *(const ulonglong2*)&sy[q * 64 + qg];
        #pragma unroll
        for (int k = 0; k < 4; k++) { ffma2(o2[k][0], g2.x, tp[k]); ffma2(o2[k][1], g2.y, tp[k]); }
    }
    float* O = out + (size_t)slice * 4096;
    #pragma unroll
    for (int k = 0; k < 4; k++)
        *(ulonglong2*)(O + (ig + k) * 64 + qg) = make_ulonglong2(o2[k][0], o2[k][1]);
}

// ---------------- launcher ----------------
extern "C" void kernel_launch(void* const* d_in, const int* in_sizes, int n_in,
                              void* d_out, int out_size) {
    const float* x     = (const float*)d_in[0];
    const float* w     = (const float*)d_in[1];
    const float* alpha = (const float*)d_in[2];
    float* out = (float*)d_out;

    cudaFuncSetAttribute(conv_mma_kernel,
                         cudaFuncAttributeMaxDynamicSharedMemorySize, CONV_SMEM);

    wa_kernel<<<9 * 256, 256>>>(w);
    ginv_kernel<<<CCH, 128>>>(alpha);
    xt_kernel<<<dim3(64, 4, 32), 256>>>(x);
    conv_mma_kernel<<<dim3(16, 2, 32), 256, CONV_SMEM>>>();
    arma_solve_kernel<<<BSZ * CCH, 256>>>(out);
}

// round 6
// speedup vs baseline: 2.8604x; 1.1148x over previous
#include <cuda_runtime.h>
#include <cuda_bf16.h>
#include <math.h>

// ---------------- problem constants ----------------
#define BSZ   32
#define CCH   256
#define NPIX  4096      // 64x64

// ---------------- scratch (device globals; no allocation) ----------------
__device__ __align__(16) __nv_bfloat16  g_yh[(size_t)BSZ * CCH * NPIX];   // conv out hi
__device__ __align__(16) __nv_bfloat16  g_yl[(size_t)BSZ * CCH * NPIX];   // conv out lo
__device__ __align__(16) __nv_bfloat16  g_xt_hi[(size_t)BSZ * NPIX * CCH];
__device__ __align__(16) __nv_bfloat16  g_xt_lo[(size_t)BSZ * NPIX * CCH];
__device__ __align__(16) __nv_bfloat16  g_wa_hi[9 * CCH * CCH];
__device__ __align__(16) __nv_bfloat16  g_wa_lo[9 * CCH * CCH];
__device__ float                        g_ginv[2 * CCH * 64];
__device__ __align__(16) __nv_bfloat16  g_gyT_hi[CCH * 4096];  // GyT[c][j][q]
__device__ __align__(16) __nv_bfloat16  g_gyT_lo[CCH * 4096];
__device__ __align__(16) __nv_bfloat16  g_gx_hi[CCH * 4096];   // Gx[c][i][h]
__device__ __align__(16) __nv_bfloat16  g_gx_lo[CCH * 4096];

// ---------------- helpers ----------------
__device__ __forceinline__ unsigned smem_u32(const void* p) {
    unsigned r;
    asm("{ .reg .u64 t; cvta.to.shared.u64 t, %1; cvt.u32.u64 %0, t; }" : "=r"(r) : "l"(p));
    return r;
}
__device__ __forceinline__ unsigned sw128(unsigned off) { return off ^ ((off >> 3) & 0x70); }

__device__ __forceinline__ void ldm_x4(unsigned* r, unsigned addr) {
    asm volatile("ldmatrix.sync.aligned.m8n8.x4.shared.b16 {%0,%1,%2,%3}, [%4];"
        : "=r"(r[0]), "=r"(r[1]), "=r"(r[2]), "=r"(r[3]) : "r"(addr));
}
__device__ __forceinline__ void mma16816(float* d, const unsigned* a,
                                         unsigned b0, unsigned b1) {
    asm volatile("mma.sync.aligned.m16n8k16.row.col.f32.bf16.bf16.f32 "
        "{%0,%1,%2,%3}, {%4,%5,%6,%7}, {%8,%9}, {%0,%1,%2,%3};"
        : "+f"(d[0]), "+f"(d[1]), "+f"(d[2]), "+f"(d[3])
        : "r"(a[0]), "r"(a[1]), "r"(a[2]), "r"(a[3]), "r"(b0), "r"(b1));
}
__device__ __forceinline__ void cp16(unsigned dst, const void* src) {
    asm volatile("cp.async.cg.shared.global [%0], [%1], 16;" :: "r"(dst), "l"(src));
}
__device__ __forceinline__ void cp16z(unsigned dst, const void* src, bool ok) {
    int sz = ok ? 16 : 0;
    asm volatile("cp.async.cg.shared.global [%0], [%1], 16, %2;"
                 :: "r"(dst), "l"(src), "r"(sz));
}
__device__ __forceinline__ void cp_commit() {
    asm volatile("cp.async.commit_group;" ::: "memory");
}
__device__ __forceinline__ void cp_wait0() {
    asm volatile("cp.async.wait_group 0;" ::: "memory");
}
// split a float pair into packed bf16x2 hi + lo words
__device__ __forceinline__ void split2(float a, float b, unsigned& uh, unsigned& ul) {
    __nv_bfloat16 ha = __float2bfloat16(a), hb = __float2bfloat16(b);
    float ra = a - __bfloat162float(ha), rb = b - __bfloat162float(hb);
    __nv_bfloat16 la = __float2bfloat16(ra), lb = __float2bfloat16(rb);
    uh = (unsigned)__bfloat16_as_ushort(ha) | ((unsigned)__bfloat16_as_ushort(hb) << 16);
    ul = (unsigned)__bfloat16_as_ushort(la) | ((unsigned)__bfloat16_as_ushort(lb) << 16);
}

// ---------------- kernel 1: weights -> [tap][co][ci] bf16 hi/lo ----------------
__global__ void wa_kernel(const float* __restrict__ w) {
    int tap = blockIdx.x >> 8;
    int co  = blockIdx.x & 255;
    int ci  = threadIdx.x;
    float v = w[((size_t)co * 256 + ci) * 9 + tap];
    __nv_bfloat16 h = __float2bfloat16(v);
    __nv_bfloat16 l = __float2bfloat16(v - __bfloat162float(h));
    size_t o = ((size_t)tap * 256 + co) * 256 + ci;
    g_wa_hi[o] = h; g_wa_lo[o] = l;
}

// ---------------- kernel 2: x -> transposed bf16 hi/lo ----------------
__global__ void xt_kernel(const float* __restrict__ x) {
    __shared__ float s[64][65];
    int p0  = blockIdx.x * 64;
    int ci0 = blockIdx.y * 64;
    int b   = blockIdx.z;
    int tid = threadIdx.x;
    for (int i = tid; i < 4096; i += 256) {
        int ci = i >> 6, p = i & 63;
        s[ci][p] = x[((size_t)(b * 256 + ci0 + ci)) * NPIX + p0 + p];
    }
    __syncthreads();
    for (int i = tid; i < 4096; i += 256) {
        int pix = i >> 6, ci = i & 63;
        float v = s[ci][pix];
        __nv_bfloat16 h = __float2bfloat16(v);
        __nv_bfloat16 l = __float2bfloat16(v - __bfloat162float(h));
        size_t o = ((size_t)b * NPIX + p0 + pix) * 256 + ci0 + ci;
        g_xt_hi[o] = h; g_xt_lo[o] = l;
    }
}

// ---------------- kernel 3: circulant inverse kernels ----------------
__global__ void ginv_kernel(const float* __restrict__ alpha) {
    int c = blockIdx.x;
    int t = threadIdx.x;
    int dir = t >> 6;
    int n   = t & 63;
    float t00 = tanhf(alpha[c*4+0]), t01 = tanhf(alpha[c*4+1]);
    float t10 = tanhf(alpha[c*4+2]), t11 = tanhf(alpha[c*4+3]);
    const float R = 0.70710678118654752440f;
    float a0, a2;
    if (dir == 0) { a0 = (t00 + t01) * R; a2 = (t01 - t00) * R; }
    else          { a0 = (t10 + t11) * R; a2 = (t11 - t10) * R; }
    double ar = (double)a0 + (double)a2;
    double ai = (double)a0 - (double)a2;
    double s = 0.0;
    for (int u = 0; u < 64; u++) {
        double th  = (2.0 * 3.14159265358979323846 / 64.0) * (double)u;
        double Fre = 1.0 + ar * cos(th);
        double Fim = ai * sin(th);
        double den = Fre * Fre + Fim * Fim;
        double ang = th * (double)n;
        s += (cos(ang) * Fre + sin(ang) * Fim) / den;
    }
    g_ginv[(dir * CCH + c) * 64 + n] = (float)(s / 64.0);
}

// ---------------- kernel 3b: circulant matrices (bf16 hi/lo) ----------------
__global__ void gmat_kernel() {
    int c   = blockIdx.x;
    int tid = threadIdx.x;
    __shared__ float gx[64], gy[64];
    if (tid < 64)                 gx[tid]      = g_ginv[c * 64 + tid];
    else if (tid < 128)           gy[tid - 64] = g_ginv[(CCH + c) * 64 + (tid - 64)];
    __syncthreads();
    for (int i = tid; i < 4096; i += 256) {
        int r = i >> 6, q = i & 63;
        float vx = gx[(r - q) & 63];   // Gx[i][h]  = gx[(i-h)&63]
        float vy = gy[(r - q) & 63];   // GyT[j][q] = gy[(j-q)&63]
        __nv_bfloat16 h = __float2bfloat16(vx);
        g_gx_hi[(size_t)c * 4096 + i] = h;
        g_gx_lo[(size_t)c * 4096 + i] = __float2bfloat16(vx - __bfloat162float(h));
        h = __float2bfloat16(vy);
        g_gyT_hi[(size_t)c * 4096 + i] = h;
        g_gyT_lo[(size_t)c * 4096 + i] = __float2bfloat16(vy - __bfloat162float(h));
    }
}

// ---------------- kernel 4: implicit-GEMM conv via mma.sync ----------------
#define XPAT_ROWS  (6 * 68)
#define XPAT_BYTES (XPAT_ROWS * 128)   // 52224
#define OFF_XH 0u
#define OFF_XL (OFF_XH + XPAT_BYTES)
#define OFF_A0 (OFF_XL + XPAT_BYTES)
#define A_BUF  32768u
#define A_LO   16384u
#define CONV_SMEM (OFF_A0 + 2 * A_BUF) // 169984

__global__ __launch_bounds__(256, 1)
void conv_mma_kernel() {
    extern __shared__ char smem[];
    const unsigned sb = smem_u32(smem);
    const int tid = threadIdx.x;
    const int lid = tid & 31;
    const int wid = tid >> 5;
    const int wm  = wid & 1;
    const int wn  = wid >> 1;

    const int n0  = blockIdx.x * 256;
    const int h0  = n0 >> 6;
    const int co0 = blockIdx.y * 128;
    const int b   = blockIdx.z;

    const __nv_bfloat16* xh = g_xt_hi + (size_t)b * NPIX * 256;
    const __nv_bfloat16* xl = g_xt_lo + (size_t)b * NPIX * 256;

    float acc[4][8][4];
    #pragma unroll
    for (int mt = 0; mt < 4; mt++)
        #pragma unroll
        for (int nt = 0; nt < 8; nt++)
            #pragma unroll
            for (int k = 0; k < 4; k++) acc[mt][nt][k] = 0.f;

    unsigned a_rowoff[4];
    #pragma unroll
    for (int mt = 0; mt < 4; mt++) {
        int row = wm * 64 + mt * 16 + (lid & 7) + ((lid >> 3) & 1) * 8;
        a_rowoff[mt] = (unsigned)(row * 128) + ((unsigned)(lid >> 4)) * 16u;
    }
    int bn[4];
    #pragma unroll
    for (int j = 0; j < 4; j++) bn[j] = wn * 64 + j * 16 + (lid & 15);
    const unsigned bk8 = ((unsigned)(lid >> 4)) * 16u;

    auto stageA = [&](int tap, int ci0, int s) {
        unsigned dH = sb + OFF_A0 + (unsigned)s * A_BUF;
        unsigned dL = dH + A_LO;
        #pragma unroll
        for (int i = tid; i < 1024; i += 256) {
            int cq = i & 7, row = i >> 3;
            size_t src = ((size_t)tap * 256 + co0 + row) * 256 + ci0 + cq * 8;
            unsigned swo = sw128((unsigned)(row * 128 + cq * 16));
            cp16(dH + swo, g_wa_hi + src);
            cp16(dL + swo, g_wa_lo + src);
        }
        cp_commit();
    };

    for (int cc = 0; cc < 4; cc++) {
        const int ci0 = cc << 6;
        __syncthreads();    // previous chunk's compute done (XPAT + A free)
        // ---- stage X patch via cp.async (zero-fill for halo) ----
        for (int i = tid; i < 6 * 66 * 8; i += 256) {
            int cq  = i & 7;
            int row = i >> 3;
            int hl  = row / 66;
            int wv  = row - hl * 66;
            int h = h0 + hl - 1;
            int w = wv - 1;
            bool ok = ((unsigned)h < 64u) && ((unsigned)w < 64u);
            size_t src = ok ? (((size_t)(h * 64 + w)) * 256 + ci0 + cq * 8) : 0;
            unsigned swo = sw128((unsigned)((hl * 68 + wv) * 128 + cq * 16));
            cp16z(sb + OFF_XH + swo, xh + src, ok);
            cp16z(sb + OFF_XL + swo, xl + src, ok);
        }
        stageA(0, ci0, 0);   // commits X + A(tap0)
        cp_wait0();
        __syncthreads();

        for (int tap = 0; tap < 9; tap++) {
            const int s  = tap & 1;
            const int dh = tap / 3 - 1;
            const int dw = tap % 3 - 1;
            if (tap < 8) stageA(tap + 1, ci0, s ^ 1);

            const unsigned AH = sb + OFF_A0 + (unsigned)s * A_BUF;
            const unsigned AL = AH + A_LO;

            unsigned b_rowoff[4];
            #pragma unroll
            for (int j = 0; j < 4; j++) {
                int hl = bn[j] >> 6, w = bn[j] & 63;
                b_rowoff[j] = (unsigned)(((hl + dh + 1) * 68 + (w + dw + 1)) * 128) + bk8;
            }

            #pragma unroll
            for (int ks = 0; ks < 4; ks++) {
                unsigned afH[4][4], afL[4][4], bfH[4][4], bfL[4][4];
                #pragma unroll
                for (int mt = 0; mt < 4; mt++)
                    ldm_x4(afH[mt], AH + sw128(a_rowoff[mt] + ks * 32u));
                #pragma unroll
                for (int j = 0; j < 4; j++)
                    ldm_x4(bfH[j], sb + OFF_XH + sw128(b_rowoff[j] + ks * 32u));
                #pragma unroll
                for (int mt = 0; mt < 4; mt++)
                    #pragma unroll
                    for (int nt = 0; nt < 8; nt++)
                        mma16816(acc[mt][nt], afH[mt],
                                 bfH[nt >> 1][nt & 1], bfH[nt >> 1][(nt & 1) + 2]);
                #pragma unroll
                for (int j = 0; j < 4; j++)
                    ldm_x4(bfL[j], sb + OFF_XL + sw128(b_rowoff[j] + ks * 32u));
                #pragma unroll
                for (int mt = 0; mt < 4; mt++)
                    #pragma unroll
                    for (int nt = 0; nt < 8; nt++)
                        mma16816(acc[mt][nt], afH[mt],
                                 bfL[nt >> 1][nt & 1], bfL[nt >> 1][(nt & 1) + 2]);
                #pragma unroll
                for (int mt = 0; mt < 4; mt++)
                    ldm_x4(afL[mt], AL + sw128(a_rowoff[mt] + ks * 32u));
                #pragma unroll
                for (int mt = 0; mt < 4; mt++)
                    #pragma unroll
                    for (int nt = 0; nt < 8; nt++)
                        mma16816(acc[mt][nt], afL[mt],
                                 bfH[nt >> 1][nt & 1], bfH[nt >> 1][(nt & 1) + 2]);
            }
            if (tap < 8) {
                cp_wait0();
                __syncthreads();
            }
        }
    }

    // ---- epilogue: store y as bf16 hi/lo pairs ----
    const int r4 = lid >> 2, c2 = (lid & 3) << 1;
    #pragma unroll
    for (int mt = 0; mt < 4; mt++) {
        #pragma unroll
        for (int nt = 0; nt < 8; nt++) {
            int co  = co0 + wm * 64 + mt * 16 + r4;
            int pix = n0 + wn * 64 + nt * 8 + c2;
            size_t base = ((size_t)(b * 256 + co)) * NPIX + pix;
            unsigned uh, ul;
            split2(acc[mt][nt][0], acc[mt][nt][1], uh, ul);
            *(unsigned*)(g_yh + base) = uh;
            *(unsigned*)(g_yl + base) = ul;
            split2(acc[mt][nt][2], acc[mt][nt][3], uh, ul);
            *(unsigned*)(g_yh + base + (size_t)8 * NPIX) = uh;
            *(unsigned*)(g_yl + base + (size_t)8 * NPIX) = ul;
        }
    }
}

// ---------------- kernel 5: ARMA solve via mma.sync ----------------
// Per slice: UT[j][h] = sum_q GyT[j][q] * Y[h][q]   (A=GyT rows, B=Y rows)
//            out[i][j] = sum_h Gx[i][h] * UT[j][h]  (A=Gx rows,  B=UT rows)
// All operands bf16 hi/lo, 3-term products, fp32 accum. 128 threads, 4 warps.
#define AOFF_YH  0u
#define AOFF_YL  8192u
#define AOFF_GYH 16384u
#define AOFF_GYL 24576u
#define AOFF_GXH 32768u
#define AOFF_GXL 40960u
#define AOFF_UTH 49152u
#define AOFF_UTL 57344u
#define ARMA_SMEM 65536

__global__ __launch_bounds__(128, 3)
void arma_mma_kernel(float* __restrict__ out) {
    extern __shared__ char smem[];
    const unsigned sb = smem_u32(smem);
    const int tid = threadIdx.x;
    const int lid = tid & 31;
    const int wid = tid >> 5;
    const int slice = blockIdx.x;
    const int c = slice & 255;

    const __nv_bfloat16* Yh  = g_yh    + (size_t)slice * 4096;
    const __nv_bfloat16* Yl  = g_yl    + (size_t)slice * 4096;
    const __nv_bfloat16* GYh = g_gyT_hi + (size_t)c * 4096;
    const __nv_bfloat16* GYl = g_gyT_lo + (size_t)c * 4096;
    const __nv_bfloat16* GXh = g_gx_hi  + (size_t)c * 4096;
    const __nv_bfloat16* GXl = g_gx_lo  + (size_t)c * 4096;

    for (int i = tid; i < 512; i += 128) {
        int r = i >> 3, cq = i & 7;
        unsigned swo = sw128((unsigned)(r * 128 + cq * 16));
        int e = r * 64 + cq * 8;
        cp16(sb + AOFF_YH  + swo, Yh  + e);
        cp16(sb + AOFF_YL  + swo, Yl  + e);
        cp16(sb + AOFF_GYH + swo, GYh + e);
        cp16(sb + AOFF_GYL + swo, GYl + e);
        cp16(sb + AOFF_GXH + swo, GXh + e);
        cp16(sb + AOFF_GXL + swo, GXl + e);
    }
    cp_commit(); cp_wait0();
    __syncthreads();

    const int m0 = wid * 16;
    const unsigned a_off = (unsigned)((m0 + (lid & 7) + ((lid >> 3) & 1) * 8) * 128)
                         + ((unsigned)(lid >> 4)) * 16u;
    unsigned b_off[4];
    #pragma unroll
    for (int j = 0; j < 4; j++)
        b_off[j] = (unsigned)((j * 16 + (lid & 15)) * 128) + ((unsigned)(lid >> 4)) * 16u;

    // ---- stage 1: UT = GyT x Y^T-form ----
    float acc[8][4];
    #pragma unroll
    for (int nt = 0; nt < 8; nt++)
        #pragma unroll
        for (int k = 0; k < 4; k++) acc[nt][k] = 0.f;

    #pragma unroll
    for (int ks = 0; ks < 4; ks++) {
        unsigned AH[4], AL[4], BH[4][4], BL[4][4];
        ldm_x4(AH, sb + AOFF_GYH + sw128(a_off + ks * 32u));
        ldm_x4(AL, sb + AOFF_GYL + sw128(a_off + ks * 32u));
        #pragma unroll
        for (int j = 0; j < 4; j++) ldm_x4(BH[j], sb + AOFF_YH + sw128(b_off[j] + ks * 32u));
        #pragma unroll
        for (int j = 0; j < 4; j++) ldm_x4(BL[j], sb + AOFF_YL + sw128(b_off[j] + ks * 32u));
        #pragma unroll
        for (int nt = 0; nt < 8; nt++) {
            unsigned h0b = BH[nt >> 1][nt & 1], h1b = BH[nt >> 1][(nt & 1) + 2];
            mma16816(acc[nt], AH, h0b, h1b);
            mma16816(acc[nt], AH, BL[nt >> 1][nt & 1], BL[nt >> 1][(nt & 1) + 2]);
            mma16816(acc[nt], AL, h0b, h1b);
        }
    }

    // store UT (rows j = m, cols h = n) as bf16 hi/lo
    {
        const int r4 = lid >> 2, cp2 = (lid & 3) << 1;
        #pragma unroll
        for (int nt = 0; nt < 8; nt++) {
            int h = nt * 8 + cp2;
            unsigned uh, ul;
            split2(acc[nt][0], acc[nt][1], uh, ul);
            unsigned ad = sw128((unsigned)((m0 + r4) * 128 + h * 2));
            *(unsigned*)(smem + AOFF_UTH + ad) = uh;
            *(unsigned*)(smem + AOFF_UTL + ad) = ul;
            split2(acc[nt][2], acc[nt][3], uh, ul);
            ad = sw128((unsigned)((m0 + r4 + 8) * 128 + h * 2));
            *(unsigned*)(smem + AOFF_UTH + ad) = uh;
            *(unsigned*)(smem + AOFF_UTL + ad) = ul;
        }
    }
    __syncthreads();

    // ---- stage 2: out = Gx x UT^T-form ----
    float o[8][4];
    #pragma unroll
    for (int nt = 0; nt < 8; nt++)
        #pragma unroll
        for (int k = 0; k < 4; k++) o[nt][k] = 0.f;

    #pragma unroll
    for (int ks = 0; ks < 4; ks++) {
        unsigned AH[4], AL[4], BH[4][4], BL[4][4];
        ldm_x4(AH, sb + AOFF_GXH + sw128(a_off + ks * 32u));
        ldm_x4(AL, sb + AOFF_GXL + sw128(a_off + ks * 32u));
        #pragma unroll
        for (int j = 0; j < 4; j++) ldm_x4(BH[j], sb + AOFF_UTH + sw128(b_off[j] + ks * 32u));
        #pragma unroll
        for (int j = 0; j < 4; j++) ldm_x4(BL[j], sb + AOFF_UTL + sw128(b_off[j] + ks * 32u));
        #pragma unroll
        for (int nt = 0; nt < 8; nt++) {
            unsigned h0b = BH[nt >> 1][nt & 1], h1b = BH[nt >> 1][(nt & 1) + 2];
            mma16816(o[nt], AH, h0b, h1b);
            mma16816(o[nt], AH, BL[nt >> 1][nt & 1], BL[nt >> 1][(nt & 1) + 2]);
            mma16816(o[nt], AL, h0b, h1b);
        }
    }

    float* O = out + (size_t)slice * 4096;
    {
        const int r4 = lid >> 2, cp2 = (lid & 3) << 1;
        #pragma unroll
        for (int nt = 0; nt < 8; nt++) {
            int j = nt * 8 + cp2;
            *(float2*)(O + (m0 + r4) * 64 + j)     = make_float2(o[nt][0], o[nt][1]);
            *(float2*)(O + (m0 + r4 + 8) * 64 + j) = make_float2(o[nt][2], o[nt][3]);
        }
    }
}

// ---------------- launcher ----------------
extern "C" void kernel_launch(void* const* d_in, const int* in_sizes, int n_in,
                              void* d_out, int out_size) {
    const float* x     = (const float*)d_in[0];
    const float* w     = (const float*)d_in[1];
    const float* alpha = (const float*)d_in[2];
    float* out = (float*)d_out;

    cudaFuncSetAttribute(conv_mma_kernel,
                         cudaFuncAttributeMaxDynamicSharedMemorySize, CONV_SMEM);
    cudaFuncSetAttribute(arma_mma_kernel,
                         cudaFuncAttributeMaxDynamicSharedMemorySize, ARMA_SMEM);

    wa_kernel<<<9 * 256, 256>>>(w);
    ginv_kernel<<<CCH, 128>>>(alpha);
    gmat_kernel<<<CCH, 256>>>();
    xt_kernel<<<dim3(64, 4, 32), 256>>>(x);
    conv_mma_kernel<<<dim3(16, 2, 32), 256, CONV_SMEM>>>();
    arma_mma_kernel<<<BSZ * CCH, 128, ARMA_SMEM>>>(out);
}